// round 5
// baseline (speedup 1.0000x reference)
#include <cuda_runtime.h>

#define B_ 8
#define N_ 2000
#define F_ 128
#define K_ 64
#define MS_ 4          // m-reduction chunks
#define CHUNK_ 500     // N_/MS_

// -------- device scratch --------
__device__ float g_P[B_*N_*K_];       // masked softmax(s)  [b,n,k]
__device__ float g_Q[B_*N_];          // sum_k P^2          [b,n]
__device__ float g_OUTADJ[B_*K_*K_];  // raw S^T A S (atomic accum)
__device__ float g_SS[B_*K_*K_];      // P^T P (atomic accum)
__device__ float g_DEN[B_];
__device__ float g_LOSS[2*B_];

// -------- init: zero accumulators + out region of d_out --------
__global__ void k_init(float* __restrict__ out_region) {
    int i = blockIdx.x * blockDim.x + threadIdx.x;
    if (i < B_*K_*F_) out_region[i] = 0.f;
    if (i < B_*K_*K_) { g_OUTADJ[i] = 0.f; g_SS[i] = 0.f; }
    if (i < B_) g_DEN[i] = 0.f;
}

// -------- softmax over K=64, one warp per row --------
__global__ void k_softmax(const float* __restrict__ s,
                          const int* __restrict__ mask) {
    int row = (blockIdx.x * blockDim.x + threadIdx.x) >> 5;
    if (row >= B_*N_) return;
    int lane = threadIdx.x & 31;
    const float* sr = s + (size_t)row * K_;
    float v0 = sr[lane], v1 = sr[lane + 32];
    float mx = fmaxf(v0, v1);
    #pragma unroll
    for (int o = 16; o; o >>= 1) mx = fmaxf(mx, __shfl_xor_sync(0xffffffffu, mx, o));
    float e0 = expf(v0 - mx), e1 = expf(v1 - mx);
    float sm = e0 + e1;
    #pragma unroll
    for (int o = 16; o; o >>= 1) sm += __shfl_xor_sync(0xffffffffu, sm, o);
    float m = (mask[row] != 0) ? 1.f : 0.f;
    float inv = m / sm;
    float p0 = e0 * inv, p1 = e1 * inv;
    g_P[(size_t)row * K_ + lane]      = p0;
    g_P[(size_t)row * K_ + lane + 32] = p1;
    float q = p0 * p0 + p1 * p1;
    #pragma unroll
    for (int o = 16; o; o >>= 1) q += __shfl_xor_sync(0xffffffffu, q, o);
    if (lane == 0) g_Q[row] = q;
}

// -------- out[b,k,f] = P^T x  AND  ss = P^T P (fused) --------
__global__ void __launch_bounds__(256) k_outss_gemm(const float* __restrict__ x,
                                                    float* __restrict__ out) {
    int b = blockIdx.y;
    int row0 = blockIdx.x * 128;
    int rows = min(128, N_ - row0);
    __shared__ float Ps[32][64];
    __shared__ float Xs[32][128];
    int tid = threadIdx.x;
    int kq = tid & 15;    // 16 k-groups * 4
    int fq = tid >> 4;    // 16 f-groups * 8  (also l-groups * 4 for ss)
    float acc[4][8] = {};
    float accS[4][4] = {};
    const float* Pb = g_P + (size_t)b * N_ * K_ + (size_t)row0 * K_;
    const float* Xb = x   + (size_t)b * N_ * F_ + (size_t)row0 * F_;
    for (int t0 = 0; t0 < rows; t0 += 32) {
        #pragma unroll
        for (int i = 0; i < 8; i++) {
            int idx = tid + i * 256;
            int r = idx >> 6, c = idx & 63;
            Ps[r][c] = (t0 + r < rows) ? Pb[(size_t)(t0 + r) * K_ + c] : 0.f;
        }
        #pragma unroll
        for (int i = 0; i < 16; i++) {
            int idx = tid + i * 256;
            int r = idx >> 7, c = idx & 127;
            Xs[r][c] = (t0 + r < rows) ? Xb[(size_t)(t0 + r) * F_ + c] : 0.f;
        }
        __syncthreads();
        #pragma unroll 8
        for (int m = 0; m < 32; m++) {
            float4 pv  = *(const float4*)&Ps[m][kq * 4];
            float4 pl  = *(const float4*)&Ps[m][fq * 4];
            float4 xv0 = *(const float4*)&Xs[m][fq * 8];
            float4 xv1 = *(const float4*)&Xs[m][fq * 8 + 4];
            float a[4]  = {pv.x, pv.y, pv.z, pv.w};
            float p[4]  = {pl.x, pl.y, pl.z, pl.w};
            float bb[8] = {xv0.x, xv0.y, xv0.z, xv0.w, xv1.x, xv1.y, xv1.z, xv1.w};
            #pragma unroll
            for (int i = 0; i < 4; i++) {
                #pragma unroll
                for (int j = 0; j < 8; j++)
                    acc[i][j] = fmaf(a[i], bb[j], acc[i][j]);
                #pragma unroll
                for (int j = 0; j < 4; j++)
                    accS[i][j] = fmaf(a[i], p[j], accS[i][j]);
            }
        }
        __syncthreads();
    }
    float* ob = out + (size_t)b * K_ * F_;
    #pragma unroll
    for (int i = 0; i < 4; i++)
        #pragma unroll
        for (int j = 0; j < 8; j++)
            atomicAdd(&ob[(kq * 4 + i) * F_ + fq * 8 + j], acc[i][j]);
    float* SSb = g_SS + b * K_ * K_;
    #pragma unroll
    for (int i = 0; i < 4; i++)
        #pragma unroll
        for (int j = 0; j < 4; j++)
            atomicAdd(&SSb[(kq * 4 + i) * K_ + fq * 4 + j], accS[i][j]);
}

// -------- fused: partial AS = adj(:,chunk)@P, then out_adj += AS^T P,
//          den += sum d*q.  grid (16 rowtiles, MS_ chunks, B_) --------
__global__ void __launch_bounds__(256) k_adj_fused(const float* __restrict__ adj) {
    int b    = blockIdx.z;
    int c0   = blockIdx.y * CHUNK_;
    int row0 = blockIdx.x * 128;
    int rows = min(128, N_ - row0);
    __shared__ float As[32][132];   // phase1: adj^T tile; phase2: AS 32-row slab
    __shared__ float Ps[32][64];    // phase1: P m-rows;   phase2: P n-rows
    __shared__ float red[256];
    int tid = threadIdx.x;
    int rg = tid & 31;   // 32 row-groups * 4
    int cg = tid >> 5;   // 8 col-groups * 8
    float acc[4][8] = {};
    float dsum = 0.f;
    const float* Ab = adj + (size_t)b * N_ * N_;
    const float* Pb = g_P + (size_t)b * N_ * K_;
    int cend = c0 + CHUNK_;

    for (int m0 = c0; m0 < cend; m0 += 32) {
        #pragma unroll
        for (int l = 0; l < 4; l++) {
            int lin = tid + l * 256;          // 0..1023
            int mg = lin & 7;                 // 8 m-groups of 4
            int r  = lin >> 3;                // 0..127
            float4 v = make_float4(0.f, 0.f, 0.f, 0.f);
            int gm = m0 + mg * 4;
            if (r < rows && gm < cend)        // chunk tail is multiple of 4
                v = *(const float4*)&Ab[(size_t)(row0 + r) * N_ + gm];
            As[mg * 4 + 0][r] = v.x;
            As[mg * 4 + 1][r] = v.y;
            As[mg * 4 + 2][r] = v.z;
            As[mg * 4 + 3][r] = v.w;
        }
        #pragma unroll
        for (int i = 0; i < 8; i++) {
            int idx = tid + i * 256;
            int r = idx >> 6, c = idx & 63;
            Ps[r][c] = (m0 + r < cend) ? Pb[(size_t)(m0 + r) * K_ + c] : 0.f;
        }
        __syncthreads();

        if (tid < 128) {                      // degree partial (zero-fill safe)
            float sd = 0.f;
            #pragma unroll
            for (int m = 0; m < 32; m++) sd += As[m][tid];
            dsum += sd;
        }
        #pragma unroll 8
        for (int m = 0; m < 32; m++) {
            float4 av = *(const float4*)&As[m][rg * 4];
            float4 b0 = *(const float4*)&Ps[m][cg * 8];
            float4 b1 = *(const float4*)&Ps[m][cg * 8 + 4];
            float a[4]  = {av.x, av.y, av.z, av.w};
            float bb[8] = {b0.x, b0.y, b0.z, b0.w, b1.x, b1.y, b1.z, b1.w};
            #pragma unroll
            for (int i = 0; i < 4; i++)
                #pragma unroll
                for (int j = 0; j < 8; j++)
                    acc[i][j] = fmaf(a[i], bb[j], acc[i][j]);
        }
        __syncthreads();
    }

    // ---- phase 2: out_adj(k,l) += sum_{n in tile} AS[n,k] * P[n,l] ----
    int kg = tid & 15;   // 16 k-groups * 4
    int lg = tid >> 4;   // 16 l-groups * 4
    float accA[4][4] = {};
    #pragma unroll
    for (int nt = 0; nt < 4; nt++) {          // 32-row slabs of the 128-row tile
        // P rows for this slab
        #pragma unroll
        for (int i = 0; i < 8; i++) {
            int idx = tid + i * 256;
            int r = idx >> 6, c = idx & 63;
            int lr = nt * 32 + r;
            Ps[r][c] = (lr < rows) ? Pb[(size_t)(row0 + lr) * K_ + c] : 0.f;
        }
        // owning threads stage their AS rows (rows >= `rows` hold zeros already)
        if ((rg >> 3) == nt) {
            #pragma unroll
            for (int i = 0; i < 4; i++)
                #pragma unroll
                for (int j = 0; j < 8; j++)
                    As[(rg & 7) * 4 + i][cg * 8 + j] = acc[i][j];
        }
        __syncthreads();
        #pragma unroll 8
        for (int n = 0; n < 32; n++) {
            float4 ak = *(const float4*)&As[n][kg * 4];
            float4 pl = *(const float4*)&Ps[n][lg * 4];
            float a[4] = {ak.x, ak.y, ak.z, ak.w};
            float p[4] = {pl.x, pl.y, pl.z, pl.w};
            #pragma unroll
            for (int i = 0; i < 4; i++)
                #pragma unroll
                for (int j = 0; j < 4; j++)
                    accA[i][j] = fmaf(a[i], p[j], accA[i][j]);
        }
        __syncthreads();
    }
    float* OA = g_OUTADJ + b * K_ * K_;
    #pragma unroll
    for (int i = 0; i < 4; i++)
        #pragma unroll
        for (int j = 0; j < 4; j++)
            atomicAdd(&OA[(kg * 4 + i) * K_ + lg * 4 + j], accA[i][j]);

    // ---- den partial: sum_n d_chunk[n] * q[n] ----
    float dq = 0.f;
    if (tid < 128 && tid < rows) dq = dsum * g_Q[b * N_ + row0 + tid];
    red[tid] = dq; __syncthreads();
    for (int st = 128; st; st >>= 1) { if (tid < st) red[tid] += red[tid + st]; __syncthreads(); }
    if (tid == 0) atomicAdd(&g_DEN[b], red[0]);
}

// -------- per-batch finalize: losses + normalized out_adj --------
__global__ void k_finalize(float* __restrict__ outadj_out) {
    int b = blockIdx.x;
    int tid = threadIdx.x;
    const float* OA  = g_OUTADJ + b * K_ * K_;
    const float* SSb = g_SS     + b * K_ * K_;
    __shared__ float red[256];
    __shared__ float s_frob, s_trace;
    __shared__ float dvec[K_];

    float fs = 0.f;
    for (int i = tid; i < K_*K_; i += 256) { float v = SSb[i]; fs += v * v; }
    red[tid] = fs; __syncthreads();
    for (int st = 128; st; st >>= 1) { if (tid < st) red[tid] += red[tid + st]; __syncthreads(); }
    if (tid == 0) s_frob = sqrtf(red[0]);
    __syncthreads();
    float frob = s_frob;

    float os = 0.f;
    for (int i = tid; i < K_*K_; i += 256) {
        int k = i >> 6, l = i & 63;
        float v = SSb[i] / frob - ((k == l) ? 0.125f : 0.f);
        os += v * v;
    }
    red[tid] = os; __syncthreads();
    for (int st = 128; st; st >>= 1) { if (tid < st) red[tid] += red[tid + st]; __syncthreads(); }
    float ortho = sqrtf(red[0]);
    __syncthreads();

    float tr = (tid < K_) ? OA[tid * K_ + tid] : 0.f;
    red[tid] = tr; __syncthreads();
    for (int st = 128; st; st >>= 1) { if (tid < st) red[tid] += red[tid + st]; __syncthreads(); }
    if (tid == 0) s_trace = red[0];
    __syncthreads();

    if (tid < K_) {
        float rs = 0.f;
        #pragma unroll
        for (int l = 0; l < K_; l++) if (l != tid) rs += OA[tid * K_ + l];
        dvec[tid] = sqrtf(rs) + 1e-15f;
    }
    __syncthreads();
    for (int i = tid; i < K_*K_; i += 256) {
        int k = i >> 6, l = i & 63;
        float v = (k == l) ? 0.f : OA[i] / (dvec[k] * dvec[l]);
        outadj_out[b * K_ * K_ + i] = v;
    }
    if (tid == 0) {
        g_LOSS[b]      = -(s_trace / g_DEN[b]);
        g_LOSS[B_ + b] = ortho;
    }
}

__global__ void k_losses(float* __restrict__ out2) {
    if (threadIdx.x == 0) {
        float a = 0.f, o = 0.f;
        #pragma unroll
        for (int b = 0; b < B_; b++) { a += g_LOSS[b]; o += g_LOSS[B_ + b]; }
        out2[0] = a * (1.f / B_);
        out2[1] = o * (1.f / B_);
    }
}

extern "C" void kernel_launch(void* const* d_in, const int* in_sizes, int n_in,
                              void* d_out, int out_size) {
    const float* x    = (const float*)d_in[0];   // [8,2000,128] f32
    const float* adj  = (const float*)d_in[1];   // [8,2000,2000] f32
    const float* s    = (const float*)d_in[2];   // [8,2000,64] f32
    const int*   mask = (const int*)d_in[3];     // [8,2000] bool->int32
    float* out = (float*)d_out;
    // layout: out [8,64,128] | out_adj [8,64,64] | mincut_loss | ortho_loss

    k_init<<<256, 256>>>(out);
    k_softmax<<<(B_*N_*32 + 255) / 256, 256>>>(s, mask);
    dim3 g2(16, B_);       k_outss_gemm<<<g2, 256>>>(x, out);
    dim3 g3(16, MS_, B_);  k_adj_fused<<<g3, 256>>>(adj);
    k_finalize<<<B_, 256>>>(out + B_*K_*F_);
    k_losses<<<1, 32>>>(out + B_*K_*F_ + B_*K_*K_);
    (void)in_sizes; (void)n_in; (void)out_size;
}

// round 8
// speedup vs baseline: 1.7656x; 1.7656x over previous
#include <cuda_runtime.h>
#include <mma.h>
#include <cstdint>

using namespace nvcuda;

#define B_ 8
#define N_ 2000
#define F_ 128
#define K_ 64
#define TK_ 32
#define NT_ ((N_ + TK_ - 1) / TK_)   // 63

// -------- device scratch --------
__device__ float g_P [B_*N_*K_];      // masked softmax(s)  [b,n,k]
__device__ float g_AS[B_*N_*K_];      // adj @ P            [b,n,k]
__device__ float g_Q [B_*N_];         // sum_k P^2
__device__ float g_D [B_*N_];         // rowsum adj
__device__ float g_OUTADJ[B_*K_*K_];
__device__ float g_SS[B_*K_*K_];
__device__ float g_DEN[B_];
__device__ float g_LOSS[2*B_];

// -------- init --------
__global__ void k_init(float* __restrict__ out_region) {
    int i = blockIdx.x * blockDim.x + threadIdx.x;
    if (i < B_*K_*F_) out_region[i] = 0.f;
    if (i < B_*K_*K_) { g_OUTADJ[i] = 0.f; g_SS[i] = 0.f; }
    if (i < B_) g_DEN[i] = 0.f;
}

// -------- softmax over K=64, one warp per row --------
__global__ void k_softmax(const float* __restrict__ s,
                          const int* __restrict__ mask) {
    int row = (blockIdx.x * blockDim.x + threadIdx.x) >> 5;
    if (row >= B_*N_) return;
    int lane = threadIdx.x & 31;
    const float* sr = s + (size_t)row * K_;
    float v0 = sr[lane], v1 = sr[lane + 32];
    float mx = fmaxf(v0, v1);
    #pragma unroll
    for (int o = 16; o; o >>= 1) mx = fmaxf(mx, __shfl_xor_sync(0xffffffffu, mx, o));
    float e0 = expf(v0 - mx), e1 = expf(v1 - mx);
    float sm = e0 + e1;
    #pragma unroll
    for (int o = 16; o; o >>= 1) sm += __shfl_xor_sync(0xffffffffu, sm, o);
    float m = (mask[row] != 0) ? 1.f : 0.f;
    float inv = m / sm;
    float p0 = e0 * inv, p1 = e1 * inv;
    g_P[(size_t)row * K_ + lane]      = p0;
    g_P[(size_t)row * K_ + lane + 32] = p1;
    float q = p0 * p0 + p1 * p1;
    #pragma unroll
    for (int o = 16; o; o >>= 1) q += __shfl_xor_sync(0xffffffffu, q, o);
    if (lane == 0) g_Q[row] = q;
}

// -------- out[b,k,f] = P^T x (scalar fp32, proven) --------
__global__ void __launch_bounds__(256) k_out_gemm(const float* __restrict__ x,
                                                  float* __restrict__ out) {
    int b = blockIdx.y;
    int row0 = blockIdx.x * 128;
    int rows = min(128, N_ - row0);
    __shared__ float Ps[32][64];
    __shared__ float Xs[32][128];
    int tid = threadIdx.x;
    int kq = tid & 15;
    int fq = tid >> 4;
    float acc[4][8] = {};
    const float* Pb = g_P + (size_t)b * N_ * K_ + (size_t)row0 * K_;
    const float* Xb = x   + (size_t)b * N_ * F_ + (size_t)row0 * F_;
    for (int t0 = 0; t0 < rows; t0 += 32) {
        #pragma unroll
        for (int i = 0; i < 8; i++) {
            int idx = tid + i * 256;
            int r = idx >> 6, c = idx & 63;
            Ps[r][c] = (t0 + r < rows) ? Pb[(size_t)(t0 + r) * K_ + c] : 0.f;
        }
        #pragma unroll
        for (int i = 0; i < 16; i++) {
            int idx = tid + i * 256;
            int r = idx >> 7, c = idx & 127;
            Xs[r][c] = (t0 + r < rows) ? Xb[(size_t)(t0 + r) * F_ + c] : 0.f;
        }
        __syncthreads();
        #pragma unroll 8
        for (int m = 0; m < 32; m++) {
            float4 pv  = *(const float4*)&Ps[m][kq * 4];
            float4 xv0 = *(const float4*)&Xs[m][fq * 8];
            float4 xv1 = *(const float4*)&Xs[m][fq * 8 + 4];
            float a[4]  = {pv.x, pv.y, pv.z, pv.w};
            float bb[8] = {xv0.x, xv0.y, xv0.z, xv0.w, xv1.x, xv1.y, xv1.z, xv1.w};
            #pragma unroll
            for (int i = 0; i < 4; i++)
                #pragma unroll
                for (int j = 0; j < 8; j++)
                    acc[i][j] = fmaf(a[i], bb[j], acc[i][j]);
        }
        __syncthreads();
    }
    float* ob = out + (size_t)b * K_ * F_;
    #pragma unroll
    for (int i = 0; i < 4; i++)
        #pragma unroll
        for (int j = 0; j < 8; j++)
            atomicAdd(&ob[(kq * 4 + i) * F_ + fq * 8 + j], acc[i][j]);
}

// -------- AS = adj @ P via wmma tf32 (+ fused degree rowsum) --------
// grid (16, B_), 256 threads = 8 warps in 4x2 layout; CTA tile 128x64.
#define APAD 36   // 32 + 4 pad (float4-aligned)
#define BPAD 68   // 64 + 4 pad

__global__ void __launch_bounds__(256) k_adj_wmma(const float* __restrict__ adj) {
    __shared__ float As[128][APAD];   // adj tile [row][kchunk]
    __shared__ float Bs[TK_][BPAD];   // P rows   [kchunk][64]
    int tid = threadIdx.x;
    int warp = tid >> 5;
    int wm = warp >> 1;               // 0..3 (M 32-tiles)
    int wn = warp & 1;                // 0..1 (N 32-tiles)
    int b = blockIdx.y;
    int row0 = blockIdx.x * 128;
    int rows = min(128, N_ - row0);   // 128 or 80 (both multiples of 16)

    const float* Ab = adj + (size_t)b * N_ * N_;
    const float* Pb = g_P + (size_t)b * N_ * K_;

    wmma::fragment<wmma::accumulator, 16, 16, 8, float> c[2][2];
    #pragma unroll
    for (int i = 0; i < 2; i++)
        #pragma unroll
        for (int j = 0; j < 2; j++) wmma::fill_fragment(c[i][j], 0.f);

    // loader mappings
    int ar = tid >> 1;                // A row 0..127
    int ac = (tid & 1) * 16;          // A col base (16 floats)
    float4 aR[4], bR[2];
    float dsum = 0.f;

    auto loadA = [&](int t) {
        int m0 = t * TK_;
        #pragma unroll
        for (int i = 0; i < 4; i++) {
            int cc = ac + i * 4;
            aR[i] = (ar < rows && m0 + cc < N_)
                  ? *(const float4*)&Ab[(size_t)(row0 + ar) * N_ + m0 + cc]
                  : make_float4(0.f, 0.f, 0.f, 0.f);
        }
    };
    auto loadB = [&](int t) {
        int m0 = t * TK_;
        #pragma unroll
        for (int i = 0; i < 2; i++) {
            int f4 = tid + i * 256;       // 0..511
            int r = f4 >> 4, c4 = (f4 & 15) * 4;
            bR[i] = (m0 + r < N_)
                  ? *(const float4*)&Pb[(size_t)(m0 + r) * K_ + c4]
                  : make_float4(0.f, 0.f, 0.f, 0.f);
        }
    };

    loadA(0); loadB(0);
    for (int t = 0; t < NT_; t++) {
        // stage regs -> smem, accumulate degree
        #pragma unroll
        for (int i = 0; i < 4; i++) {
            *(float4*)&As[ar][ac + i * 4] = aR[i];
            dsum += aR[i].x + aR[i].y + aR[i].z + aR[i].w;
        }
        #pragma unroll
        for (int i = 0; i < 2; i++) {
            int f4 = tid + i * 256;
            int r = f4 >> 4, c4 = (f4 & 15) * 4;
            *(float4*)&Bs[r][c4] = bR[i];
        }
        __syncthreads();
        if (t + 1 < NT_) { loadA(t + 1); loadB(t + 1); }   // overlap with MMA

        #pragma unroll
        for (int ks = 0; ks < 4; ks++) {
            wmma::fragment<wmma::matrix_a, 16, 16, 8, wmma::precision::tf32, wmma::row_major> af[2];
            wmma::fragment<wmma::matrix_b, 16, 16, 8, wmma::precision::tf32, wmma::row_major> bf[2];
            #pragma unroll
            for (int i = 0; i < 2; i++) {
                wmma::load_matrix_sync(af[i], &As[wm * 32 + i * 16][ks * 8], APAD);
                #pragma unroll
                for (int e = 0; e < af[i].num_elements; e++)
                    af[i].x[e] = wmma::__float_to_tf32(af[i].x[e]);
            }
            #pragma unroll
            for (int j = 0; j < 2; j++) {
                wmma::load_matrix_sync(bf[j], &Bs[ks * 8][wn * 32 + j * 16], BPAD);
                #pragma unroll
                for (int e = 0; e < bf[j].num_elements; e++)
                    bf[j].x[e] = wmma::__float_to_tf32(bf[j].x[e]);
            }
            #pragma unroll
            for (int i = 0; i < 2; i++)
                #pragma unroll
                for (int j = 0; j < 2; j++)
                    wmma::mma_sync(c[i][j], af[i], bf[j], c[i][j]);
        }
        __syncthreads();
    }

    // degree: pair-combine (both threads of a row), store
    dsum += __shfl_xor_sync(0xffffffffu, dsum, 1);
    if ((tid & 1) == 0 && ar < rows) g_D[b * N_ + row0 + ar] = dsum;

    // store fragments (rows is a multiple of 16 -> fragment-granular guard exact)
    float* ASb = g_AS + ((size_t)b * N_ + row0) * K_;
    #pragma unroll
    for (int i = 0; i < 2; i++) {
        int r = wm * 32 + i * 16;
        if (r < rows)
            #pragma unroll
            for (int j = 0; j < 2; j++)
                wmma::store_matrix_sync(&ASb[(size_t)r * K_ + wn * 32 + j * 16],
                                        c[i][j], K_, wmma::mem_row_major);
    }
}

// -------- out_adj = AS^T P, ss = P^T P, den = sum d*q --------
__global__ void __launch_bounds__(256) k_small(void) {
    int b = blockIdx.y;
    int n0 = blockIdx.x * 250;
    __shared__ float ASs[16][64];
    __shared__ float Ps[16][64];
    __shared__ float red[256];
    int tid = threadIdx.x;
    int kg = tid & 15;
    int lg = tid >> 4;
    float accA[4][4] = {};
    float accS[4][4] = {};
    const float* ASb = g_AS + (size_t)b * N_ * K_;
    const float* Pb  = g_P  + (size_t)b * N_ * K_;
    for (int t0 = 0; t0 < 250; t0 += 16) {
        #pragma unroll
        for (int i = 0; i < 4; i++) {
            int idx = tid + i * 256;
            int r = idx >> 6, c = idx & 63;
            bool ok = (t0 + r) < 250;
            size_t g = (size_t)(n0 + t0 + r) * K_ + c;
            ASs[r][c] = ok ? ASb[g] : 0.f;
            Ps[r][c]  = ok ? Pb[g]  : 0.f;
        }
        __syncthreads();
        #pragma unroll 8
        for (int m = 0; m < 16; m++) {
            float4 ak = *(const float4*)&ASs[m][kg * 4];
            float4 pk = *(const float4*)&Ps[m][kg * 4];
            float4 pl = *(const float4*)&Ps[m][lg * 4];
            float a[4] = {ak.x, ak.y, ak.z, ak.w};
            float p[4] = {pk.x, pk.y, pk.z, pk.w};
            float q[4] = {pl.x, pl.y, pl.z, pl.w};
            #pragma unroll
            for (int i = 0; i < 4; i++)
                #pragma unroll
                for (int j = 0; j < 4; j++) {
                    accA[i][j] = fmaf(a[i], q[j], accA[i][j]);
                    accS[i][j] = fmaf(p[i], q[j], accS[i][j]);
                }
        }
        __syncthreads();
    }
    float* OA  = g_OUTADJ + b * K_ * K_;
    float* SSb = g_SS     + b * K_ * K_;
    #pragma unroll
    for (int i = 0; i < 4; i++)
        #pragma unroll
        for (int j = 0; j < 4; j++) {
            atomicAdd(&OA [(kg * 4 + i) * K_ + lg * 4 + j], accA[i][j]);
            atomicAdd(&SSb[(kg * 4 + i) * K_ + lg * 4 + j], accS[i][j]);
        }
    float dq = 0.f;
    for (int n = tid; n < 250; n += 256) {
        int gi = b * N_ + n0 + n;
        dq += g_D[gi] * g_Q[gi];
    }
    red[tid] = dq; __syncthreads();
    for (int st = 128; st; st >>= 1) { if (tid < st) red[tid] += red[tid + st]; __syncthreads(); }
    if (tid == 0) atomicAdd(&g_DEN[b], red[0]);
}

// -------- per-batch finalize --------
__global__ void k_finalize(float* __restrict__ outadj_out) {
    int b = blockIdx.x;
    int tid = threadIdx.x;
    const float* OA  = g_OUTADJ + b * K_ * K_;
    const float* SSb = g_SS     + b * K_ * K_;
    __shared__ float red[256];
    __shared__ float s_frob, s_trace;
    __shared__ float dvec[K_];

    float fs = 0.f;
    for (int i = tid; i < K_*K_; i += 256) { float v = SSb[i]; fs += v * v; }
    red[tid] = fs; __syncthreads();
    for (int st = 128; st; st >>= 1) { if (tid < st) red[tid] += red[tid + st]; __syncthreads(); }
    if (tid == 0) s_frob = sqrtf(red[0]);
    __syncthreads();
    float frob = s_frob;

    float os = 0.f;
    for (int i = tid; i < K_*K_; i += 256) {
        int k = i >> 6, l = i & 63;
        float v = SSb[i] / frob - ((k == l) ? 0.125f : 0.f);
        os += v * v;
    }
    red[tid] = os; __syncthreads();
    for (int st = 128; st; st >>= 1) { if (tid < st) red[tid] += red[tid + st]; __syncthreads(); }
    float ortho = sqrtf(red[0]);
    __syncthreads();

    float tr = (tid < K_) ? OA[tid * K_ + tid] : 0.f;
    red[tid] = tr; __syncthreads();
    for (int st = 128; st; st >>= 1) { if (tid < st) red[tid] += red[tid + st]; __syncthreads(); }
    if (tid == 0) s_trace = red[0];
    __syncthreads();

    if (tid < K_) {
        float rs = 0.f;
        #pragma unroll
        for (int l = 0; l < K_; l++) if (l != tid) rs += OA[tid * K_ + l];
        dvec[tid] = sqrtf(rs) + 1e-15f;
    }
    __syncthreads();
    for (int i = tid; i < K_*K_; i += 256) {
        int k = i >> 6, l = i & 63;
        float v = (k == l) ? 0.f : OA[i] / (dvec[k] * dvec[l]);
        outadj_out[b * K_ * K_ + i] = v;
    }
    if (tid == 0) {
        g_LOSS[b]      = -(s_trace / g_DEN[b]);
        g_LOSS[B_ + b] = ortho;
    }
}

__global__ void k_losses(float* __restrict__ out2) {
    if (threadIdx.x == 0) {
        float a = 0.f, o = 0.f;
        #pragma unroll
        for (int b = 0; b < B_; b++) { a += g_LOSS[b]; o += g_LOSS[B_ + b]; }
        out2[0] = a * (1.f / B_);
        out2[1] = o * (1.f / B_);
    }
}

extern "C" void kernel_launch(void* const* d_in, const int* in_sizes, int n_in,
                              void* d_out, int out_size) {
    const float* x    = (const float*)d_in[0];   // [8,2000,128]
    const float* adj  = (const float*)d_in[1];   // [8,2000,2000]
    const float* s    = (const float*)d_in[2];   // [8,2000,64]
    const int*   mask = (const int*)d_in[3];     // [8,2000] bool->int32
    float* out = (float*)d_out;
    // layout: out [8,64,128] | out_adj [8,64,64] | mincut_loss | ortho_loss

    k_init<<<256, 256>>>(out);
    k_softmax<<<(B_*N_*32 + 255) / 256, 256>>>(s, mask);
    dim3 g2(16, B_);  k_out_gemm<<<g2, 256>>>(x, out);
    dim3 g3(16, B_);  k_adj_wmma<<<g3, 256>>>(adj);
    dim3 g4(8, B_);   k_small<<<g4, 256>>>();
    k_finalize<<<B_, 256>>>(out + B_*K_*F_);
    k_losses<<<1, 32>>>(out + B_*K_*F_ + B_*K_*K_);
    (void)in_sizes; (void)n_in; (void)out_size;
}

// round 10
// speedup vs baseline: 1.9025x; 1.0775x over previous
#include <cuda_runtime.h>
#include <mma.h>
#include <cstdint>

using namespace nvcuda;

#define B_ 8
#define N_ 2000
#define F_ 128
#define K_ 64
#define TK_ 32
#define NT_ ((N_ + TK_ - 1) / TK_)   // 63

// -------- device scratch --------
__device__ float g_P [B_*N_*K_];      // masked softmax(s)  [b,n,k]
__device__ float g_AS[B_*N_*K_];      // adj @ P            [b,n,k]
__device__ float g_Q [B_*N_];         // sum_k P^2
__device__ float g_D [B_*N_];         // rowsum adj
__device__ float g_OUTADJ[B_*K_*K_];
__device__ float g_SS[B_*K_*K_];
__device__ float g_DEN[B_];
__device__ float g_LOSS[2*B_];

// -------- init --------
__global__ void k_init(float* __restrict__ out_region) {
    int i = blockIdx.x * blockDim.x + threadIdx.x;
    if (i < B_*K_*F_) out_region[i] = 0.f;
    if (i < B_*K_*K_) { g_OUTADJ[i] = 0.f; g_SS[i] = 0.f; }
    if (i < B_) g_DEN[i] = 0.f;
}

// -------- softmax over K=64, one warp per row --------
__global__ void k_softmax(const float* __restrict__ s,
                          const int* __restrict__ mask) {
    int row = (blockIdx.x * blockDim.x + threadIdx.x) >> 5;
    if (row >= B_*N_) return;
    int lane = threadIdx.x & 31;
    const float* sr = s + (size_t)row * K_;
    float v0 = sr[lane], v1 = sr[lane + 32];
    float mx = fmaxf(v0, v1);
    #pragma unroll
    for (int o = 16; o; o >>= 1) mx = fmaxf(mx, __shfl_xor_sync(0xffffffffu, mx, o));
    float e0 = expf(v0 - mx), e1 = expf(v1 - mx);
    float sm = e0 + e1;
    #pragma unroll
    for (int o = 16; o; o >>= 1) sm += __shfl_xor_sync(0xffffffffu, sm, o);
    float m = (mask[row] != 0) ? 1.f : 0.f;
    float inv = m / sm;
    float p0 = e0 * inv, p1 = e1 * inv;
    g_P[(size_t)row * K_ + lane]      = p0;
    g_P[(size_t)row * K_ + lane + 32] = p1;
    float q = p0 * p0 + p1 * p1;
    #pragma unroll
    for (int o = 16; o; o >>= 1) q += __shfl_xor_sync(0xffffffffu, q, o);
    if (lane == 0) g_Q[row] = q;
}

// -------- out[b,k,f] = P^T x (scalar fp32), 64-row tiles, 256 CTAs --------
__global__ void __launch_bounds__(256) k_out_gemm(const float* __restrict__ x,
                                                  float* __restrict__ out) {
    int b = blockIdx.y;
    int row0 = blockIdx.x * 64;
    int rows = min(64, N_ - row0);
    __shared__ float Ps[32][64];
    __shared__ float Xs[32][128];
    int tid = threadIdx.x;
    int kq = tid & 15;
    int fq = tid >> 4;
    float acc[4][8] = {};
    const float* Pb = g_P + (size_t)b * N_ * K_ + (size_t)row0 * K_;
    const float* Xb = x   + (size_t)b * N_ * F_ + (size_t)row0 * F_;
    for (int t0 = 0; t0 < rows; t0 += 32) {
        #pragma unroll
        for (int i = 0; i < 8; i++) {
            int idx = tid + i * 256;
            int r = idx >> 6, c = idx & 63;
            Ps[r][c] = (t0 + r < rows) ? Pb[(size_t)(t0 + r) * K_ + c] : 0.f;
        }
        #pragma unroll
        for (int i = 0; i < 16; i++) {
            int idx = tid + i * 256;
            int r = idx >> 7, c = idx & 127;
            Xs[r][c] = (t0 + r < rows) ? Xb[(size_t)(t0 + r) * F_ + c] : 0.f;
        }
        __syncthreads();
        #pragma unroll 8
        for (int m = 0; m < 32; m++) {
            float4 pv  = *(const float4*)&Ps[m][kq * 4];
            float4 xv0 = *(const float4*)&Xs[m][fq * 8];
            float4 xv1 = *(const float4*)&Xs[m][fq * 8 + 4];
            float a[4]  = {pv.x, pv.y, pv.z, pv.w};
            float bb[8] = {xv0.x, xv0.y, xv0.z, xv0.w, xv1.x, xv1.y, xv1.z, xv1.w};
            #pragma unroll
            for (int i = 0; i < 4; i++)
                #pragma unroll
                for (int j = 0; j < 8; j++)
                    acc[i][j] = fmaf(a[i], bb[j], acc[i][j]);
        }
        __syncthreads();
    }
    float* ob = out + (size_t)b * K_ * F_;
    #pragma unroll
    for (int i = 0; i < 4; i++)
        #pragma unroll
        for (int j = 0; j < 8; j++)
            atomicAdd(&ob[(kq * 4 + i) * F_ + fq * 8 + j], acc[i][j]);
}

// -------- AS = adj @ P via wmma tf32, 64-row tiles, 256 CTAs --------
#define APAD 36
#define BPAD 68

__global__ void __launch_bounds__(256) k_adj_wmma(const float* __restrict__ adj) {
    __shared__ float As[64][APAD];    // adj tile [row][kchunk] (tf32-rounded)
    __shared__ float Bs[TK_][BPAD];   // P rows   [kchunk][64]  (tf32-rounded)
    int tid = threadIdx.x;
    int warp = tid >> 5;
    int wm = warp >> 1;               // 0..3 (16-row tiles)
    int wn = warp & 1;                // 0..1 (32-col tiles)
    int b = blockIdx.y;
    int row0 = blockIdx.x * 64;
    int rows = min(64, N_ - row0);    // 64 or 16 (multiples of 16)

    const float* Ab = adj + (size_t)b * N_ * N_;
    const float* Pb = g_P + (size_t)b * N_ * K_;

    wmma::fragment<wmma::accumulator, 16, 16, 8, float> c[2];
    wmma::fill_fragment(c[0], 0.f);
    wmma::fill_fragment(c[1], 0.f);

    int ar = tid >> 2;                // A row 0..63
    int ac = (tid & 3) * 8;           // A col base (8 floats = 2 float4)
    float4 aR[2], bR[2];
    float dsum = 0.f;

    auto loadA = [&](int t) {
        int m0 = t * TK_;
        #pragma unroll
        for (int i = 0; i < 2; i++) {
            int cc = ac + i * 4;
            aR[i] = (ar < rows && m0 + cc < N_)
                  ? *(const float4*)&Ab[(size_t)(row0 + ar) * N_ + m0 + cc]
                  : make_float4(0.f, 0.f, 0.f, 0.f);
        }
    };
    auto loadB = [&](int t) {
        int m0 = t * TK_;
        #pragma unroll
        for (int i = 0; i < 2; i++) {
            int f4 = tid + i * 256;
            int r = f4 >> 4, c4 = (f4 & 15) * 4;
            bR[i] = (m0 + r < N_)
                  ? *(const float4*)&Pb[(size_t)(m0 + r) * K_ + c4]
                  : make_float4(0.f, 0.f, 0.f, 0.f);
        }
    };
    auto tf32x4 = [](float4 v) {
        return make_float4(wmma::__float_to_tf32(v.x), wmma::__float_to_tf32(v.y),
                           wmma::__float_to_tf32(v.z), wmma::__float_to_tf32(v.w));
    };

    loadA(0); loadB(0);
    for (int t = 0; t < NT_; t++) {
        // stage regs -> smem (tf32-rounded), accumulate exact-fp32 degree
        #pragma unroll
        for (int i = 0; i < 2; i++) {
            dsum += aR[i].x + aR[i].y + aR[i].z + aR[i].w;
            *(float4*)&As[ar][ac + i * 4] = tf32x4(aR[i]);
        }
        #pragma unroll
        for (int i = 0; i < 2; i++) {
            int f4 = tid + i * 256;
            int r = f4 >> 4, c4 = (f4 & 15) * 4;
            *(float4*)&Bs[r][c4] = tf32x4(bR[i]);
        }
        __syncthreads();
        if (t + 1 < NT_) { loadA(t + 1); loadB(t + 1); }   // overlap with MMA

        #pragma unroll
        for (int ks = 0; ks < 4; ks++) {
            wmma::fragment<wmma::matrix_a, 16, 16, 8, wmma::precision::tf32, wmma::row_major> af;
            wmma::fragment<wmma::matrix_b, 16, 16, 8, wmma::precision::tf32, wmma::row_major> bf[2];
            wmma::load_matrix_sync(af, &As[wm * 16][ks * 8], APAD);
            #pragma unroll
            for (int j = 0; j < 2; j++)
                wmma::load_matrix_sync(bf[j], &Bs[ks * 8][wn * 32 + j * 16], BPAD);
            #pragma unroll
            for (int j = 0; j < 2; j++)
                wmma::mma_sync(c[j], af, bf[j], c[j]);
        }
        __syncthreads();
    }

    // degree: 4 threads per row -> combine via shfl (lane bits 0..1), store
    dsum += __shfl_xor_sync(0xffffffffu, dsum, 1);
    dsum += __shfl_xor_sync(0xffffffffu, dsum, 2);
    if ((tid & 3) == 0 && ar < rows) g_D[b * N_ + row0 + ar] = dsum;

    // store fragments (rows multiple of 16 -> fragment guard exact)
    float* ASb = g_AS + ((size_t)b * N_ + row0) * K_;
    int r = wm * 16;
    if (r < rows) {
        #pragma unroll
        for (int j = 0; j < 2; j++)
            wmma::store_matrix_sync(&ASb[(size_t)r * K_ + wn * 32 + j * 16],
                                    c[j], K_, wmma::mem_row_major);
    }
}

// -------- out_adj = AS^T P, ss = P^T P, den = sum d*q (125-row chunks) --------
__global__ void __launch_bounds__(256) k_small(void) {
    int b = blockIdx.y;
    int n0 = blockIdx.x * 125;
    __shared__ float ASs[16][64];
    __shared__ float Ps[16][64];
    __shared__ float red[256];
    int tid = threadIdx.x;
    int kg = tid & 15;
    int lg = tid >> 4;
    float accA[4][4] = {};
    float accS[4][4] = {};
    const float* ASb = g_AS + (size_t)b * N_ * K_;
    const float* Pb  = g_P  + (size_t)b * N_ * K_;
    for (int t0 = 0; t0 < 125; t0 += 16) {
        #pragma unroll
        for (int i = 0; i < 4; i++) {
            int idx = tid + i * 256;
            int r = idx >> 6, c = idx & 63;
            bool ok = (t0 + r) < 125;
            size_t g = (size_t)(n0 + t0 + r) * K_ + c;
            ASs[r][c] = ok ? ASb[g] : 0.f;
            Ps[r][c]  = ok ? Pb[g]  : 0.f;
        }
        __syncthreads();
        #pragma unroll 8
        for (int m = 0; m < 16; m++) {
            float4 ak = *(const float4*)&ASs[m][kg * 4];
            float4 pk = *(const float4*)&Ps[m][kg * 4];
            float4 pl = *(const float4*)&Ps[m][lg * 4];
            float a[4] = {ak.x, ak.y, ak.z, ak.w};
            float p[4] = {pk.x, pk.y, pk.z, pk.w};
            float q[4] = {pl.x, pl.y, pl.z, pl.w};
            #pragma unroll
            for (int i = 0; i < 4; i++)
                #pragma unroll
                for (int j = 0; j < 4; j++) {
                    accA[i][j] = fmaf(a[i], q[j], accA[i][j]);
                    accS[i][j] = fmaf(p[i], q[j], accS[i][j]);
                }
        }
        __syncthreads();
    }
    float* OA  = g_OUTADJ + b * K_ * K_;
    float* SSb = g_SS     + b * K_ * K_;
    #pragma unroll
    for (int i = 0; i < 4; i++)
        #pragma unroll
        for (int j = 0; j < 4; j++) {
            atomicAdd(&OA [(kg * 4 + i) * K_ + lg * 4 + j], accA[i][j]);
            atomicAdd(&SSb[(kg * 4 + i) * K_ + lg * 4 + j], accS[i][j]);
        }
    float dq = 0.f;
    for (int n = tid; n < 125; n += 256) {
        int gi = b * N_ + n0 + n;
        dq += g_D[gi] * g_Q[gi];
    }
    red[tid] = dq; __syncthreads();
    for (int st = 128; st; st >>= 1) { if (tid < st) red[tid] += red[tid + st]; __syncthreads(); }
    if (tid == 0) atomicAdd(&g_DEN[b], red[0]);
}

// -------- per-batch finalize --------
__global__ void k_finalize(float* __restrict__ outadj_out) {
    int b = blockIdx.x;
    int tid = threadIdx.x;
    const float* OA  = g_OUTADJ + b * K_ * K_;
    const float* SSb = g_SS     + b * K_ * K_;
    __shared__ float red[256];
    __shared__ float s_frob, s_trace;
    __shared__ float dvec[K_];

    float fs = 0.f;
    for (int i = tid; i < K_*K_; i += 256) { float v = SSb[i]; fs += v * v; }
    red[tid] = fs; __syncthreads();
    for (int st = 128; st; st >>= 1) { if (tid < st) red[tid] += red[tid + st]; __syncthreads(); }
    if (tid == 0) s_frob = sqrtf(red[0]);
    __syncthreads();
    float frob = s_frob;

    float os = 0.f;
    for (int i = tid; i < K_*K_; i += 256) {
        int k = i >> 6, l = i & 63;
        float v = SSb[i] / frob - ((k == l) ? 0.125f : 0.f);
        os += v * v;
    }
    red[tid] = os; __syncthreads();
    for (int st = 128; st; st >>= 1) { if (tid < st) red[tid] += red[tid + st]; __syncthreads(); }
    float ortho = sqrtf(red[0]);
    __syncthreads();

    float tr = (tid < K_) ? OA[tid * K_ + tid] : 0.f;
    red[tid] = tr; __syncthreads();
    for (int st = 128; st; st >>= 1) { if (tid < st) red[tid] += red[tid + st]; __syncthreads(); }
    if (tid == 0) s_trace = red[0];
    __syncthreads();

    if (tid < K_) {
        float rs = 0.f;
        #pragma unroll
        for (int l = 0; l < K_; l++) if (l != tid) rs += OA[tid * K_ + l];
        dvec[tid] = sqrtf(rs) + 1e-15f;
    }
    __syncthreads();
    for (int i = tid; i < K_*K_; i += 256) {
        int k = i >> 6, l = i & 63;
        float v = (k == l) ? 0.f : OA[i] / (dvec[k] * dvec[l]);
        outadj_out[b * K_ * K_ + i] = v;
    }
    if (tid == 0) {
        g_LOSS[b]      = -(s_trace / g_DEN[b]);
        g_LOSS[B_ + b] = ortho;
    }
}

__global__ void k_losses(float* __restrict__ out2) {
    if (threadIdx.x == 0) {
        float a = 0.f, o = 0.f;
        #pragma unroll
        for (int b = 0; b < B_; b++) { a += g_LOSS[b]; o += g_LOSS[B_ + b]; }
        out2[0] = a * (1.f / B_);
        out2[1] = o * (1.f / B_);
    }
}

extern "C" void kernel_launch(void* const* d_in, const int* in_sizes, int n_in,
                              void* d_out, int out_size) {
    const float* x    = (const float*)d_in[0];   // [8,2000,128]
    const float* adj  = (const float*)d_in[1];   // [8,2000,2000]
    const float* s    = (const float*)d_in[2];   // [8,2000,64]
    const int*   mask = (const int*)d_in[3];     // [8,2000] bool->int32
    float* out = (float*)d_out;
    // layout: out [8,64,128] | out_adj [8,64,64] | mincut_loss | ortho_loss

    k_init<<<256, 256>>>(out);
    k_softmax<<<(B_*N_*32 + 255) / 256, 256>>>(s, mask);
    dim3 g2(32, B_);  k_out_gemm<<<g2, 256>>>(x, out);
    dim3 g3(32, B_);  k_adj_wmma<<<g3, 256>>>(adj);
    dim3 g4(16, B_);  k_small<<<g4, 256>>>();
    k_finalize<<<B_, 256>>>(out + B_*K_*F_);
    k_losses<<<1, 32>>>(out + B_*K_*F_ + B_*K_*K_);
    (void)in_sizes; (void)n_in; (void)out_size;
}